// round 6
// baseline (speedup 1.0000x reference)
#include <cuda_runtime.h>
#include <math.h>

// Fixed problem dims
#define BB 64      // batch
#define TT 512     // time steps
#define II 512     // input dim
#define HH 1024    // hidden dim
#define OO 512     // output dim
#define MM 64      // memory word size
#define PP 1024    // memory slots
#define G3 3072    // 3*HH
#define NB 148     // persistent blocks
#define NT 256     // threads/block
#define LDS_ 66    // smem row stride (conflict-free column reads)

// Device state (allocation forbidden -> globals)
__device__ __align__(16) float g_h[2][BB * HH];
__device__ __align__(16) float g_xin[BB * II];
__device__ __align__(16) float g_gp[3][BB * G3];   // gate partials: [0]=gi, [1]+[2]=gh K-splits
__device__ __align__(16) float g_cp[8][BB * OO];   // output GEMM K-split partials
__device__ __align__(16) float g_memT[MM * PP];    // transposed memory
__device__ volatile unsigned g_gen;
__device__ unsigned g_cnt;

// ---------------------------------------------------------------------------
// Grid barrier: release fence -> arrive -> spin on generation -> acquire fence
// ---------------------------------------------------------------------------
__device__ __forceinline__ void gsync()
{
    __syncthreads();
    __threadfence();
    if (threadIdx.x == 0) {
        unsigned my = g_gen;
        if (atomicAdd(&g_cnt, 1u) == NB - 1u) {
            atomicExch(&g_cnt, 0u);
            __threadfence();
            g_gen = my + 1u;
        } else {
            while (g_gen == my) { __nanosleep(64); }
        }
    }
    __syncthreads();
    __threadfence();
}

// ---------------------------------------------------------------------------
// 64(batch) x 64(cols) x Kc GEMM partial with 4x4 register tiles.
//   outp[b*ldo + n0+n] = sum_{k<Kc} X[b*ldx + xoff+k] * W[(n0+n)*ldw + woff+k]
// ---------------------------------------------------------------------------
__device__ __forceinline__ void gemm64(
    const float* __restrict__ X, int ldx, int xoff,
    const float* __restrict__ W, int ldw, int woff,
    int n0, int Kc, float* __restrict__ outp, int ldo,
    float* __restrict__ xs, float* __restrict__ ws)
{
    const int tid = threadIdx.x;
    const int ty  = tid & 15;        // batch rows ty, ty+16, ty+32, ty+48
    const int tx  = tid >> 4;        // cols      tx, tx+16, tx+32, tx+48

    float acc[4][4];
    #pragma unroll
    for (int i = 0; i < 4; i++)
        #pragma unroll
        for (int j = 0; j < 4; j++) acc[i][j] = 0.f;

    for (int k0 = 0; k0 < Kc; k0 += 64) {
        // Stage 64x64 tiles of X and W (coalesced float4 loads)
        #pragma unroll
        for (int q = 0; q < 4; q++) {
            int idx = tid + q * NT;          // 0..1023 float4 slots
            int r   = idx >> 4;              // row 0..63
            int kk  = (idx & 15) << 2;       // k 0..60 step 4
            float4 a = *(const float4*)(X + (size_t)r * ldx + xoff + k0 + kk);
            float4 b = *(const float4*)(W + (size_t)(n0 + r) * ldw + woff + k0 + kk);
            float* xd = xs + r * LDS_ + kk;  // 8B-aligned (66*4 % 8 == 0)
            float* wd = ws + r * LDS_ + kk;
            ((float2*)xd)[0] = make_float2(a.x, a.y);
            ((float2*)xd)[1] = make_float2(a.z, a.w);
            ((float2*)wd)[0] = make_float2(b.x, b.y);
            ((float2*)wd)[1] = make_float2(b.z, b.w);
        }
        __syncthreads();

        const float* x0 = xs + ty * LDS_;
        const float* w0 = ws + tx * LDS_;
        #pragma unroll 8
        for (int k = 0; k < 64; k++) {
            float xv0 = x0[k];
            float xv1 = x0[16 * LDS_ + k];
            float xv2 = x0[32 * LDS_ + k];
            float xv3 = x0[48 * LDS_ + k];
            float wv0 = w0[k];
            float wv1 = w0[16 * LDS_ + k];
            float wv2 = w0[32 * LDS_ + k];
            float wv3 = w0[48 * LDS_ + k];
            acc[0][0] += xv0 * wv0; acc[0][1] += xv0 * wv1; acc[0][2] += xv0 * wv2; acc[0][3] += xv0 * wv3;
            acc[1][0] += xv1 * wv0; acc[1][1] += xv1 * wv1; acc[1][2] += xv1 * wv2; acc[1][3] += xv1 * wv3;
            acc[2][0] += xv2 * wv0; acc[2][1] += xv2 * wv1; acc[2][2] += xv2 * wv2; acc[2][3] += xv2 * wv3;
            acc[3][0] += xv3 * wv0; acc[3][1] += xv3 * wv1; acc[3][2] += xv3 * wv2; acc[3][3] += xv3 * wv3;
        }
        __syncthreads();
    }

    #pragma unroll
    for (int i = 0; i < 4; i++) {
        float* orow = outp + (size_t)(ty + i * 16) * ldo + n0 + tx;
        #pragma unroll
        for (int j = 0; j < 4; j++) orow[j * 16] = acc[i][j];
    }
}

// ---------------------------------------------------------------------------
// Phase A (block b): content read + softmax + relu projection -> g_xin
// ---------------------------------------------------------------------------
__device__ void phaseA(int b, int t,
                       const float* __restrict__ hcur,
                       const float* __restrict__ x,
                       const float* __restrict__ mem,
                       const float* __restrict__ Wk,
                       const float* __restrict__ bk,
                       const float* __restrict__ Wri,
                       const float* __restrict__ bri,
                       float* sm)
{
    float* hs    = sm;          // 1024
    float* ex    = sm + 1024;   // 1024
    float* kq    = sm + 2048;   // 64
    float* red   = sm + 2112;   // 256
    float* readv = sm + 2368;   // 64
    float* sred  = sm + 2432;   // 16

    const int tid  = threadIdx.x;
    const int warp = tid >> 5;
    const int lane = tid & 31;

    for (int i = tid; i < HH; i += NT) hs[i] = hcur[b * HH + i];
    __syncthreads();

    // kq[m] = h . Wk[m,:] + bk[m]
    #pragma unroll
    for (int mi = 0; mi < 8; mi++) {
        int m = warp * 8 + mi;
        const float* wrow = Wk + (size_t)m * HH;
        float s = 0.f;
        for (int k = lane; k < HH; k += 32) s += hs[k] * wrow[k];
        #pragma unroll
        for (int off = 16; off; off >>= 1) s += __shfl_down_sync(0xffffffffu, s, off);
        if (lane == 0) kq[m] = s + bk[m];
    }
    __syncthreads();

    // scores over 1024 slots (4/thread) from transposed memory (coalesced)
    float s0 = 0.f, s1 = 0.f, s2 = 0.f, s3 = 0.f;
    const float* mt = g_memT + tid;
    #pragma unroll 8
    for (int m = 0; m < MM; m++) {
        float kv = kq[m];
        const float* row = mt + m * PP;
        s0 += kv * row[0];
        s1 += kv * row[256];
        s2 += kv * row[512];
        s3 += kv * row[768];
    }
    float lmax = fmaxf(fmaxf(s0, s1), fmaxf(s2, s3));
    #pragma unroll
    for (int off = 16; off; off >>= 1)
        lmax = fmaxf(lmax, __shfl_xor_sync(0xffffffffu, lmax, off));
    if (lane == 0) sred[warp] = lmax;
    __syncthreads();
    float bmax = sred[0];
    #pragma unroll
    for (int w = 1; w < 8; w++) bmax = fmaxf(bmax, sred[w]);

    float e0 = expf(s0 - bmax), e1 = expf(s1 - bmax);
    float e2 = expf(s2 - bmax), e3 = expf(s3 - bmax);
    ex[tid] = e0; ex[tid + 256] = e1; ex[tid + 512] = e2; ex[tid + 768] = e3;
    float lsum = e0 + e1 + e2 + e3;
    #pragma unroll
    for (int off = 16; off; off >>= 1)
        lsum += __shfl_xor_sync(0xffffffffu, lsum, off);
    if (lane == 0) sred[8 + warp] = lsum;
    __syncthreads();
    float bsum = 0.f;
    #pragma unroll
    for (int w = 0; w < 8; w++) bsum += sred[8 + w];

    // read[m] = sum_p ex[p]*mem[p,m] / bsum  (coalesced over m)
    {
        int m = tid & 63;
        int q = tid >> 6;
        const float* mp = mem + (size_t)(q * 256) * MM + m;
        const float* ep = ex + q * 256;
        float pr = 0.f;
        #pragma unroll 4
        for (int p = 0; p < 256; p++) pr += ep[p] * mp[(size_t)p * MM];
        red[q * 64 + m] = pr;
    }
    __syncthreads();
    if (tid < MM)
        readv[tid] = (red[tid] + red[64 + tid] + red[128 + tid] + red[192 + tid]) / bsum;
    __syncthreads();

    // xin = x_t + relu(read . Wri[i,:] + bri[i])
    const float* xrow = x + ((size_t)b * TT + t) * II;
    for (int i = tid; i < II; i += NT) {
        const float4* wr = (const float4*)(Wri + (size_t)i * MM);
        float s = bri[i];
        #pragma unroll
        for (int m4 = 0; m4 < 16; m4++) {
            float4 w = wr[m4];
            s += readv[m4 * 4 + 0] * w.x + readv[m4 * 4 + 1] * w.y
               + readv[m4 * 4 + 2] * w.z + readv[m4 * 4 + 3] * w.w;
        }
        g_xin[b * II + i] = xrow[i] + fmaxf(s, 0.f);
    }
}

// ---------------------------------------------------------------------------
// Persistent megakernel
// ---------------------------------------------------------------------------
__global__ void __launch_bounds__(NT, 1) ntm_persist(
    const float* __restrict__ x,    const float* __restrict__ mem,
    const float* __restrict__ Wk,   const float* __restrict__ bk,
    const float* __restrict__ Wri,  const float* __restrict__ bri,
    const float* __restrict__ Wih,  const float* __restrict__ Whh,
    const float* __restrict__ bih,  const float* __restrict__ bhh,
    const float* __restrict__ Wout, const float* __restrict__ bout,
    float* __restrict__ out)
{
    __shared__ __align__(16) float sm[2 * 64 * LDS_];   // 33792 B
    float* xs = sm;
    float* ws = sm + 64 * LDS_;

    const int bid = blockIdx.x;
    const int gid = bid * NT + threadIdx.x;

    // Init: h0 = 0; transpose memory
    for (int e = gid; e < BB * HH; e += NB * NT) g_h[0][e] = 0.f;
    for (int e = gid; e < PP * MM; e += NB * NT) {
        int p = e >> 6, m = e & 63;
        g_memT[m * PP + p] = mem[e];
    }
    gsync();

    for (int t = 0; t <= TT; t++) {
        const float* hcur = g_h[t & 1];      // h(t) == h_new(t-1)

        // ---- slot1: phaseA(t) || output GEMM(t-1) ----
        if (t < TT && bid < 64) {
            phaseA(bid, t, hcur, x, mem, Wk, bk, Wri, bri, sm);
        } else if (t >= 1 && bid >= 64 && bid < 128) {
            int job = bid - 64;              // 0..63
            int nt = job & 7, ks = job >> 3; // 8 n-tiles x 8 k-splits(128)
            gemm64(hcur, HH, ks * 128, Wout, HH, ks * 128,
                   nt * 64, 128, g_cp[ks], OO, xs, ws);
        }
        gsync();

        // ---- slot2: gate GEMM(t) || output combine(t-1) ----
        if (bid < 144) {
            if (t < TT) {
                if (bid < 48) {
                    gemm64(g_xin, II, 0, Wih, II, 0,
                           bid * 64, II, g_gp[0], G3, xs, ws);
                } else {
                    int job = bid - 48;            // 0..95
                    int nt = job % 48, ks = job / 48;
                    gemm64(hcur, HH, ks * 512, Whh, HH, ks * 512,
                           nt * 64, 512, g_gp[1 + ks], G3, xs, ws);
                }
            }
        } else if (t >= 1) {
            int idx = (bid - 144) * NT + threadIdx.x;   // 0..1023
            for (int e = idx; e < BB * OO; e += 4 * NT) {
                int b = e >> 9, oc = e & (OO - 1);
                float s = bout[oc];
                #pragma unroll
                for (int q = 0; q < 8; q++) s += g_cp[q][e];
                out[((size_t)b * TT + (t - 1)) * OO + oc] = 1.f / (1.f + expf(-s));
            }
        }
        if (t == TT) break;                  // nothing left after final output
        gsync();

        // ---- slot3: GRU combine -> h(t+1) ----
        {
            float* hnew = g_h[(t + 1) & 1];
            for (int e = gid; e < BB * HH; e += NB * NT) {
                int b = e >> 10, c = e & 1023;
                const float* p0 = g_gp[0] + (size_t)b * G3;
                const float* p1 = g_gp[1] + (size_t)b * G3;
                const float* p2 = g_gp[2] + (size_t)b * G3;
                float ir  = p0[c]        + bih[c];
                float iz  = p0[1024 + c] + bih[1024 + c];
                float inn = p0[2048 + c] + bih[2048 + c];
                float hr  = p1[c]        + p2[c]        + bhh[c];
                float hz  = p1[1024 + c] + p2[1024 + c] + bhh[1024 + c];
                float hn  = p1[2048 + c] + p2[2048 + c] + bhh[2048 + c];
                float rg = 1.f / (1.f + expf(-(ir + hr)));
                float zg = 1.f / (1.f + expf(-(iz + hz)));
                float ng = tanhf(inn + rg * hn);
                hnew[e] = (1.f - zg) * ng + zg * hcur[e];
            }
        }
        gsync();
    }
}

// ---------------------------------------------------------------------------
// Single launch -> single graph node
// ---------------------------------------------------------------------------
extern "C" void kernel_launch(void* const* d_in, const int* in_sizes, int n_in,
                              void* d_out, int out_size)
{
    const float* x    = (const float*)d_in[0];
    const float* mem  = (const float*)d_in[1];
    const float* Wk   = (const float*)d_in[2];
    const float* bk   = (const float*)d_in[3];
    const float* Wri  = (const float*)d_in[4];
    const float* bri  = (const float*)d_in[5];
    const float* Wih  = (const float*)d_in[6];
    const float* Whh  = (const float*)d_in[7];
    const float* bih  = (const float*)d_in[8];
    const float* bhh  = (const float*)d_in[9];
    const float* Wout = (const float*)d_in[10];
    const float* bout = (const float*)d_in[11];

    ntm_persist<<<NB, NT>>>(x, mem, Wk, bk, Wri, bri, Wih, Whh,
                            bih, bhh, Wout, bout, (float*)d_out);
}

// round 7
// speedup vs baseline: 1.2163x; 1.2163x over previous
#include <cuda_runtime.h>
#include <math.h>

// Fixed problem dims
#define BB 64      // batch
#define TT 512     // time steps
#define II 512     // input dim
#define HH 1024    // hidden dim
#define OO 512     // output dim
#define MM 64      // memory word size
#define PP 1024    // memory slots
#define G3 3072    // 3*HH
#define NB 148     // persistent blocks (<= SM count)
#define NT 512     // threads/block (16 warps)
#define LDS_ 68    // smem row stride in floats (float4-aligned, conflict-free)

// Device state (allocation forbidden -> globals)
__device__ __align__(16) float g_h[2][BB * HH];
__device__ __align__(16) float g_xin[BB * II];
__device__ __align__(16) float g_gp[6][BB * G3];   // gate partials: [0..1]=gi ksplits, [2..5]=gh ksplits
__device__ __align__(16) float g_cp[16][BB * OO];  // output GEMM K-split partials
__device__ __align__(16) float g_memT[MM * PP];    // transposed memory
__device__ volatile unsigned g_gen;
__device__ unsigned g_cnt;

// ---------------------------------------------------------------------------
// Grid barrier
// ---------------------------------------------------------------------------
__device__ __forceinline__ void gsync()
{
    __syncthreads();
    __threadfence();
    if (threadIdx.x == 0) {
        unsigned my = g_gen;
        if (atomicAdd(&g_cnt, 1u) == NB - 1u) {
            atomicExch(&g_cnt, 0u);
            __threadfence();
            g_gen = my + 1u;
        } else {
            while (g_gen == my) { __nanosleep(64); }
        }
    }
    __syncthreads();
    __threadfence();
}

// ---------------------------------------------------------------------------
// 64(batch) x 128(cols) x Kc GEMM partial, 512 threads, 4x4/thread,
// float4 LDS inner loop, register-double-buffered global staging.
//   outp[b*ldo + n0+n] = sum_{k<Kc} X[b*ldx + xoff+k] * W[(n0+n)*ldw + woff+k]
// ---------------------------------------------------------------------------
__device__ __forceinline__ void gemm128(
    const float* __restrict__ X, int ldx, int xoff,
    const float* __restrict__ W, int ldw, int woff,
    int n0, int Kc, float* __restrict__ outp, int ldo,
    float* __restrict__ xs, float* __restrict__ ws)
{
    const int tid = threadIdx.x;
    const int ty  = tid & 15;        // rows ty, ty+16, ty+32, ty+48
    const int tx  = tid >> 4;        // cols tx, tx+32, tx+64, tx+96 (tx 0..31)

    float acc[4][4];
    #pragma unroll
    for (int i = 0; i < 4; i++)
        #pragma unroll
        for (int j = 0; j < 4; j++) acc[i][j] = 0.f;

    float4 ra[2], rb[4];
    // prefetch chunk 0
    #pragma unroll
    for (int q = 0; q < 2; q++) {
        int idx = tid + q * NT, r = idx >> 4, kk = (idx & 15) << 2;
        ra[q] = *(const float4*)(X + (size_t)r * ldx + xoff + kk);
    }
    #pragma unroll
    for (int q = 0; q < 4; q++) {
        int idx = tid + q * NT, r = idx >> 4, kk = (idx & 15) << 2;
        rb[q] = *(const float4*)(W + (size_t)(n0 + r) * ldw + woff + kk);
    }

    const int nch = Kc >> 6;
    for (int c = 0; c < nch; c++) {
        // stage current chunk
        #pragma unroll
        for (int q = 0; q < 2; q++) {
            int idx = tid + q * NT, r = idx >> 4, kk = (idx & 15) << 2;
            *(float4*)(xs + r * LDS_ + kk) = ra[q];
        }
        #pragma unroll
        for (int q = 0; q < 4; q++) {
            int idx = tid + q * NT, r = idx >> 4, kk = (idx & 15) << 2;
            *(float4*)(ws + r * LDS_ + kk) = rb[q];
        }
        __syncthreads();

        // prefetch next chunk while computing this one
        if (c + 1 < nch) {
            int k0 = (c + 1) << 6;
            #pragma unroll
            for (int q = 0; q < 2; q++) {
                int idx = tid + q * NT, r = idx >> 4, kk = (idx & 15) << 2;
                ra[q] = *(const float4*)(X + (size_t)r * ldx + xoff + k0 + kk);
            }
            #pragma unroll
            for (int q = 0; q < 4; q++) {
                int idx = tid + q * NT, r = idx >> 4, kk = (idx & 15) << 2;
                rb[q] = *(const float4*)(W + (size_t)(n0 + r) * ldw + woff + k0 + kk);
            }
        }

        const float* x0 = xs + ty * LDS_;
        const float* w0 = ws + tx * LDS_;
        #pragma unroll
        for (int k4 = 0; k4 < 16; k4++) {
            float4 xv[4], wv[4];
            #pragma unroll
            for (int i = 0; i < 4; i++)
                xv[i] = *(const float4*)(x0 + i * 16 * LDS_ + k4 * 4);
            #pragma unroll
            for (int j = 0; j < 4; j++)
                wv[j] = *(const float4*)(w0 + j * 32 * LDS_ + k4 * 4);
            #pragma unroll
            for (int i = 0; i < 4; i++)
                #pragma unroll
                for (int j = 0; j < 4; j++)
                    acc[i][j] += xv[i].x * wv[j].x + xv[i].y * wv[j].y
                               + xv[i].z * wv[j].z + xv[i].w * wv[j].w;
        }
        __syncthreads();
    }

    #pragma unroll
    for (int i = 0; i < 4; i++) {
        float* orow = outp + (size_t)(ty + i * 16) * ldo + n0 + tx;
        #pragma unroll
        for (int j = 0; j < 4; j++) orow[j * 32] = acc[i][j];
    }
}

// ---------------------------------------------------------------------------
// Phase A (block b, 512 threads): content read + softmax + relu proj -> g_xin
// ---------------------------------------------------------------------------
__device__ void phaseA(int b, int t,
                       const float* __restrict__ hcur,
                       const float* __restrict__ x,
                       const float* __restrict__ mem,
                       const float* __restrict__ Wk,
                       const float* __restrict__ bk,
                       const float* __restrict__ Wri,
                       const float* __restrict__ bri,
                       float* sm)
{
    float* hs    = sm;          // 1024
    float* ex    = sm + 1024;   // 1024
    float* kq    = sm + 2048;   // 64
    float* red   = sm + 2112;   // 512 (8 groups x 64)
    float* readv = sm + 2624;   // 64
    float* sred  = sm + 2688;   // 32

    const int tid  = threadIdx.x;
    const int warp = tid >> 5;   // 0..15
    const int lane = tid & 31;

    hs[tid]       = hcur[b * HH + tid];
    hs[tid + 512] = hcur[b * HH + tid + 512];
    __syncthreads();

    // kq[m] = h . Wk[m,:] + bk[m]   (16 warps x 4 rows)
    #pragma unroll
    for (int mi = 0; mi < 4; mi++) {
        int m = warp * 4 + mi;
        const float* wrow = Wk + (size_t)m * HH;
        float s = 0.f;
        for (int k = lane; k < HH; k += 32) s += hs[k] * wrow[k];
        #pragma unroll
        for (int off = 16; off; off >>= 1) s += __shfl_down_sync(0xffffffffu, s, off);
        if (lane == 0) kq[m] = s + bk[m];
    }
    __syncthreads();

    // scores over 1024 slots (2/thread) from transposed memory
    float s0 = 0.f, s1 = 0.f;
    const float* mt = g_memT + tid;
    #pragma unroll 8
    for (int m = 0; m < MM; m++) {
        float kv = kq[m];
        const float* row = mt + m * PP;
        s0 += kv * row[0];
        s1 += kv * row[512];
    }
    float lmax = fmaxf(s0, s1);
    #pragma unroll
    for (int off = 16; off; off >>= 1)
        lmax = fmaxf(lmax, __shfl_xor_sync(0xffffffffu, lmax, off));
    if (lane == 0) sred[warp] = lmax;
    __syncthreads();
    float bmax = sred[0];
    #pragma unroll
    for (int w = 1; w < 16; w++) bmax = fmaxf(bmax, sred[w]);

    float e0 = expf(s0 - bmax), e1 = expf(s1 - bmax);
    ex[tid] = e0; ex[tid + 512] = e1;
    float lsum = e0 + e1;
    #pragma unroll
    for (int off = 16; off; off >>= 1)
        lsum += __shfl_xor_sync(0xffffffffu, lsum, off);
    if (lane == 0) sred[16 + warp] = lsum;
    __syncthreads();
    float bsum = 0.f;
    #pragma unroll
    for (int w = 0; w < 16; w++) bsum += sred[16 + w];

    // read[m] = sum_p ex[p]*mem[p,m] / bsum  (8 p-groups of 128)
    {
        int m = tid & 63;
        int q = tid >> 6;                 // 0..7
        const float* mp = mem + (size_t)(q * 128) * MM + m;
        const float* ep = ex + q * 128;
        float pr = 0.f;
        #pragma unroll 4
        for (int p = 0; p < 128; p++) pr += ep[p] * mp[(size_t)p * MM];
        red[q * 64 + m] = pr;
    }
    __syncthreads();
    if (tid < MM) {
        float s = 0.f;
        #pragma unroll
        for (int q = 0; q < 8; q++) s += red[q * 64 + tid];
        readv[tid] = s / bsum;
    }
    __syncthreads();

    // xin = x_t + relu(read . Wri[i,:] + bri[i])   (1 col/thread)
    {
        int i = tid;
        const float4* wr = (const float4*)(Wri + (size_t)i * MM);
        float s = bri[i];
        #pragma unroll
        for (int m4 = 0; m4 < 16; m4++) {
            float4 w = wr[m4];
            s += readv[m4 * 4 + 0] * w.x + readv[m4 * 4 + 1] * w.y
               + readv[m4 * 4 + 2] * w.z + readv[m4 * 4 + 3] * w.w;
        }
        g_xin[b * II + i] = x[((size_t)b * TT + t) * II + i] + fmaxf(s, 0.f);
    }
}

// ---------------------------------------------------------------------------
// Persistent megakernel
// ---------------------------------------------------------------------------
__global__ void __launch_bounds__(NT, 1) ntm_persist(
    const float* __restrict__ x,    const float* __restrict__ mem,
    const float* __restrict__ Wk,   const float* __restrict__ bk,
    const float* __restrict__ Wri,  const float* __restrict__ bri,
    const float* __restrict__ Wih,  const float* __restrict__ Whh,
    const float* __restrict__ bih,  const float* __restrict__ bhh,
    const float* __restrict__ Wout, const float* __restrict__ bout,
    float* __restrict__ out)
{
    extern __shared__ __align__(16) float sm[];   // 52,224 B
    float* xs = sm;                  // 64 x 68
    float* ws = sm + 64 * LDS_;      // 128 x 68

    const int bid = blockIdx.x;
    const int gid = bid * NT + threadIdx.x;

    // Init: h0 = 0; transpose memory
    for (int e = gid; e < BB * HH; e += NB * NT) g_h[0][e] = 0.f;
    for (int e = gid; e < PP * MM; e += NB * NT) {
        int p = e >> 6, m = e & 63;
        g_memT[m * PP + p] = mem[e];
    }
    gsync();

    for (int t = 0; t <= TT; t++) {
        const float* hcur = g_h[t & 1];      // h(t) == h_new(t-1)

        // ---- slot1: phaseA(t) [0..63]  ||  out GEMM(t-1) [64..127] ----
        if (t < TT && bid < 64) {
            phaseA(bid, t, hcur, x, mem, Wk, bk, Wri, bri, sm);
        } else if (t >= 1 && bid >= 64 && bid < 128) {
            int job = bid - 64;               // 0..63: 4 n-tiles x 16 k-splits(64)
            int nt = job & 3, ks = job >> 2;
            gemm128(hcur, HH, ks * 64, Wout, HH, ks * 64,
                    nt * 128, 64, g_cp[ks], OO, xs, ws);
        }
        gsync();

        // ---- slot2: gate GEMM(t) [0..143] || out combine(t-1) [144..147] ----
        if (bid < 144) {
            if (t < TT) {
                if (bid < 48) {               // gi: 24 n-tiles x 2 k-splits(256)
                    int nt = bid >> 1, ks = bid & 1;
                    gemm128(g_xin, II, ks * 256, Wih, II, ks * 256,
                            nt * 128, 256, g_gp[ks], G3, xs, ws);
                } else {                      // gh: 24 n-tiles x 4 k-splits(256)
                    int j = bid - 48;
                    int nt = j % 24, ks = j / 24;
                    gemm128(hcur, HH, ks * 256, Whh, HH, ks * 256,
                            nt * 128, 256, g_gp[2 + ks], G3, xs, ws);
                }
            }
        } else if (t >= 1) {
            int idx = (bid - 144) * NT + threadIdx.x;   // 0..2047
            for (int e = idx; e < BB * OO; e += 4 * NT) {
                int b = e >> 9, oc = e & (OO - 1);
                float s = bout[oc];
                #pragma unroll
                for (int q = 0; q < 16; q++) s += g_cp[q][e];
                out[((size_t)b * TT + (t - 1)) * OO + oc] = 1.f / (1.f + expf(-s));
            }
        }
        if (t == TT) break;
        gsync();

        // ---- slot3: GRU combine -> h(t+1) ----
        {
            float* hnew = g_h[(t + 1) & 1];
            for (int e = gid; e < BB * HH; e += NB * NT) {
                int b = e >> 10, c = e & 1023;
                size_t o = (size_t)b * G3 + c;
                float ir  = g_gp[0][o]        + g_gp[1][o]        + bih[c];
                float iz  = g_gp[0][o + 1024] + g_gp[1][o + 1024] + bih[1024 + c];
                float inn = g_gp[0][o + 2048] + g_gp[1][o + 2048] + bih[2048 + c];
                float hr  = g_gp[2][o]        + g_gp[3][o]        + g_gp[4][o]        + g_gp[5][o]        + bhh[c];
                float hz  = g_gp[2][o + 1024] + g_gp[3][o + 1024] + g_gp[4][o + 1024] + g_gp[5][o + 1024] + bhh[1024 + c];
                float hn  = g_gp[2][o + 2048] + g_gp[3][o + 2048] + g_gp[4][o + 2048] + g_gp[5][o + 2048] + bhh[2048 + c];
                float rg = 1.f / (1.f + expf(-(ir + hr)));
                float zg = 1.f / (1.f + expf(-(iz + hz)));
                float ng = tanhf(inn + rg * hn);
                hnew[e] = (1.f - zg) * ng + zg * hcur[e];
            }
        }
        gsync();
    }
}

// ---------------------------------------------------------------------------
// Single launch -> single graph node
// ---------------------------------------------------------------------------
extern "C" void kernel_launch(void* const* d_in, const int* in_sizes, int n_in,
                              void* d_out, int out_size)
{
    const float* x    = (const float*)d_in[0];
    const float* mem  = (const float*)d_in[1];
    const float* Wk   = (const float*)d_in[2];
    const float* bk   = (const float*)d_in[3];
    const float* Wri  = (const float*)d_in[4];
    const float* bri  = (const float*)d_in[5];
    const float* Wih  = (const float*)d_in[6];
    const float* Whh  = (const float*)d_in[7];
    const float* bih  = (const float*)d_in[8];
    const float* bhh  = (const float*)d_in[9];
    const float* Wout = (const float*)d_in[10];
    const float* bout = (const float*)d_in[11];

    static int smem_set = 0;
    const int smem_bytes = (64 + 128) * LDS_ * 4;   // 52,224
    if (!smem_set) {
        cudaFuncSetAttribute(ntm_persist,
                             cudaFuncAttributeMaxDynamicSharedMemorySize,
                             smem_bytes);
        smem_set = 1;
    }

    ntm_persist<<<NB, NT, smem_bytes>>>(x, mem, Wk, bk, Wri, bri, Wih, Whh,
                                        bih, bhh, Wout, bout, (float*)d_out);
}